// round 17
// baseline (speedup 1.0000x reference)
#include <cuda_runtime.h>
#include <math.h>
#include <stdint.h>

// Problem constants
#define B_ 256
#define R_ 1152
#define C_ 10
#define O_ 16
#define I_ 8
#define RT_ 4                 // r's per tile
#define RPC_ (R_/RT_)         // 288 tiles per c
#define NT_ (RPC_*C_)         // 2880 tiles total
#define NM_ (NT_*RT_)         // 11520 rl-rows (m-index, c-major: c = m/1152)
#define G0_  444              // MODE0 grid: 148 x 3
#define G12_ 296              // MODE1/2 grid: 148 x 2

// dynamic smem layout: Wb[ROWS*32 float4] then Xr[2*4*256 float4]
#define ROWS0_  28            // max rows/block, MODE0 (ceil(2880/444)=7 tiles)
#define ROWS12_ 40            // max rows/block, MODE1/2 (10 tiles)
#define XR_F4_  (2*4*256)     // 2048 float4 = 32 KB
#define SMEM0_  ((ROWS0_*32  + XR_F4_)*16)   // 46.. KB
#define SMEM12_ ((ROWS12_*32 + XR_F4_)*16)   // 53248 B (needs opt-in)

// ---------------- device scratch (no allocations allowed) ----------------
__device__ float g_xT[R_*B_*I_];       // x transposed: [r][b][i]
__device__ float g_Wp[R_*C_*I_*O_];    // W reformatted: [r][c][i][o]
__device__ float g_b1[R_*C_*B_];       // b1 logits: float2 @ m*128+bg
__device__ float g_S[C_*O_*B_];        // numerator accumulator: [c][o][b]
__device__ float g_E[C_*B_];           // softmax denominator:   [c][b]
__device__ float g_v[B_*C_*O_];        // squashed v: [b][c][o]

typedef unsigned long long u64;

// ---------------- packed f32x2 helpers ----------------
__device__ __forceinline__ u64 pk2(float lo, float hi){
    u64 r; asm("mov.b64 %0,{%1,%2};" : "=l"(r) : "f"(lo), "f"(hi)); return r;
}
__device__ __forceinline__ void upk2(u64 v, float& lo, float& hi){
    asm("mov.b64 {%0,%1},%2;" : "=f"(lo), "=f"(hi) : "l"(v));
}
__device__ __forceinline__ u64 ffma2(u64 a, u64 b, u64 c){
    u64 d; asm("fma.rn.f32x2 %0,%1,%2,%3;" : "=l"(d) : "l"(a), "l"(b), "l"(c)); return d;
}
__device__ __forceinline__ u64 fadd2(u64 a, u64 b){
    u64 d; asm("add.rn.f32x2 %0,%1,%2;" : "=l"(d) : "l"(a), "l"(b)); return d;
}

// ---------------- cp.async helpers ----------------
__device__ __forceinline__ void cp16(uint32_t s, const void* g){
    asm volatile("cp.async.ca.shared.global [%0], [%1], 16;" :: "r"(s), "l"(g));
}
#define CP_COMMIT() asm volatile("cp.async.commit_group;")
#define CP_WAIT1()  asm volatile("cp.async.wait_group 1;" ::: "memory")
#define CP_WAIT2()  asm volatile("cp.async.wait_group 2;" ::: "memory")

// ---------------- combined prep kernel ----------------
#define XT_BLOCKS 288
#define PREP_BLOCKS (XT_BLOCKS + 720)

__global__ void __launch_bounds__(256) prep_kernel(const float* __restrict__ x,
                                                   const float* __restrict__ W){
    if (blockIdx.x < XT_BLOCKS){
        __shared__ __align__(16) float4 p0[32][33];
        __shared__ __align__(16) float4 p1[32][33];
        const int rt = blockIdx.x >> 3, bt = blockIdx.x & 7;
        const int r0 = rt*32, b0 = bt*32;
        const int w = threadIdx.x >> 5, lane = threadIdx.x & 31;
#pragma unroll
        for (int k = 0; k < 4; k++){
            int bl = w*4 + k;
            const float4* src = reinterpret_cast<const float4*>(
                x + ((b0+bl)*R_ + r0 + lane)*I_);
            p0[bl][lane] = src[0];
            p1[bl][lane] = src[1];
        }
        __syncthreads();
#pragma unroll
        for (int k = 0; k < 4; k++){
            int rl = w*4 + k;
            float4* dst = reinterpret_cast<float4*>(
                g_xT + ((r0+rl)*B_ + b0 + lane)*I_);
            dst[0] = p0[lane][rl];
            dst[1] = p1[lane][rl];
        }
    } else {
        int t = (blockIdx.x - XT_BLOCKS)*256 + threadIdx.x;
        int o = t % O_; int rc = t / O_;
        const float* src = W + t*I_;
        float* dst = g_Wp + rc*(I_*O_);
#pragma unroll
        for (int i = 0; i < I_; i++) dst[i*O_ + o] = src[i];
        if (t < C_*O_*B_) g_S[t] = 0.f;
        if (t < C_*B_)    g_E[t] = 0.f;
    }
}

// ---------------- fused routing pass ----------------
// 256 threads: tid = bg*2 + oh; bg in [0,128), oh in [0,2).
// Thread handles b_k = bg + 128k (k=0,1) and o in [oh*8, oh*8+8).
// W for the whole block range staged once (dynamic smem); x streamed via
// PER-THREAD cp.async ring (depth 2) -> no block-wide sync in the mainloop.
// Single c-boundary mc precomputed -> no division / c-compare per row.
template<int MODE>
__global__ void __launch_bounds__(256, (MODE==0)?3:2) pass_kernel(){
    extern __shared__ __align__(16) float4 dynsm[];
    constexpr int ROWSMAX = (MODE==0) ? ROWS0_ : ROWS12_;
    float4* Wb = dynsm;                       // ROWSMAX*32 float4
    float4* Xr = dynsm + ROWSMAX*32;          // 2*4*256 float4

    const int k_  = blockIdx.x;
    const int G   = gridDim.x;
    const int m0  = ((k_    * NT_) / G) * RT_;
    const int m1  = (((k_+1)* NT_) / G) * RT_;
    const int tid = threadIdx.x;
    const int bg  = tid >> 1, oh = tid & 1;

    const int cA = m0 / 1152;
    const int cB = (m1 - 1) / 1152;
    const int mc = (cA == cB) ? -1 : cB*1152;           // the single c boundary

    // ---- stage W for [m0, m1) : group 1 ----
    uint32_t wsb = (uint32_t)__cvta_generic_to_shared(Wb);
    const float4* gW4 = reinterpret_cast<const float4*>(g_Wp);
    const int nW = (m1 - m0)*32;
    for (int idx = tid; idx < nW; idx += 256){
        int m = m0 + (idx >> 5), w = idx & 31;
        int c = (mc >= 0 && m >= mc) ? cB : cA;
        int r = m - c*1152;
        cp16(wsb + (uint32_t)idx*16, &gW4[(r*C_ + c)*32 + w]);
    }
    CP_COMMIT();

    // ---- x ring prologue: rows m0 (slot 0), m0+1 (slot 1) : groups 2,3 ----
    uint32_t xrb = (uint32_t)__cvta_generic_to_shared(Xr);
    auto issue_x = [&](int r, int s){
        const char* pa = (const char*)(g_xT + (r*B_ + bg)*I_);
        const char* pb = (const char*)(g_xT + (r*B_ + bg + 128)*I_);
        uint32_t d = xrb + (uint32_t)(s*1024 + tid)*16;
        cp16(d,           pa);
        cp16(d + 256*16,  pa + 16);
        cp16(d + 512*16,  pb);
        cp16(d + 768*16,  pb + 16);
    };
    auto rOf = [&](int m){ int c = (mc >= 0 && m >= mc) ? cB : cA; return m - c*1152; };

    issue_x(rOf(m0), 0);    CP_COMMIT();
    {
        int mm = (m0+1 < m1) ? m0+1 : m0;
        issue_x(rOf(mm), 1); CP_COMMIT();
    }
    CP_WAIT2();             // W complete (own thread)
    __syncthreads();        // all threads' W complete — the ONLY block sync

    u64 u[8], S[8], v[8];
#pragma unroll
    for (int j = 0; j < 8; j++) S[j] = 0ull;
    float E[2] = {0.f, 0.f};
    int cc = cA;

    if (MODE){
#pragma unroll
        for (int k = 0; k < 2; k++){
            const float4* vp = reinterpret_cast<const float4*>(
                g_v + ((bg + 128*k)*C_ + cc)*O_ + oh*8);
            float4 f0 = vp[0], f1 = vp[1];
            v[k*4+0] = pk2(f0.x, f0.y); v[k*4+1] = pk2(f0.z, f0.w);
            v[k*4+2] = pk2(f1.x, f1.y); v[k*4+3] = pk2(f1.z, f1.w);
        }
    }

    // prefetch-row index for min(m0+2, m1-1)
    int pf_r = rOf((m0+2 < m1-1) ? m0+2 : m1-1);
    // b1 double buffer (MODE 2)
    float2 bq;
    if (MODE == 2) bq = *reinterpret_cast<const float2*>(g_b1 + m0*256 + bg*2);

#pragma unroll 1
    for (int m = m0; m < m1; m++){
        if (m == mc){
            // flush finished c, switch to cB
#pragma unroll
            for (int k = 0; k < 2; k++){
                int b = bg + 128*k;
#pragma unroll
                for (int q = 0; q < 4; q++){
                    float lo, hi; upk2(S[k*4+q], lo, hi);
                    int o = oh*8 + 2*q;
                    atomicAdd(&g_S[(cc*O_ + o    )*B_ + b], lo);
                    atomicAdd(&g_S[(cc*O_ + o + 1)*B_ + b], hi);
                    S[k*4+q] = 0ull;
                }
                if (MODE && oh == 0){ atomicAdd(&g_E[cc*B_ + b], E[k]); E[k] = 0.f; }
            }
            cc = cB;
            if (MODE){
#pragma unroll
                for (int k = 0; k < 2; k++){
                    const float4* vp = reinterpret_cast<const float4*>(
                        g_v + ((bg + 128*k)*C_ + cc)*O_ + oh*8);
                    float4 f0 = vp[0], f1 = vp[1];
                    v[k*4+0] = pk2(f0.x, f0.y); v[k*4+1] = pk2(f0.z, f0.w);
                    v[k*4+2] = pk2(f1.x, f1.y); v[k*4+3] = pk2(f1.z, f1.w);
                }
            }
        }

        // b1 for next row (MODE 2) — issued a full row early
        float2 bqn;
        if (MODE == 2){
            int mn = (m+1 < m1) ? m+1 : m;
            bqn = *reinterpret_cast<const float2*>(g_b1 + mn*256 + bg*2);
        }

        CP_WAIT1();                                  // row m's x ready (own thread)
        const int s = m & 1;
        float4 X0 = Xr[s*1024 +        tid];
        float4 X1 = Xr[s*1024 + 256  + tid];
        float4 X2 = Xr[s*1024 + 512  + tid];
        float4 X3 = Xr[s*1024 + 768  + tid];

        // refill this slot with row m+2 (clamped)
        issue_x(pf_r, s); CP_COMMIT();
        if (m + 2 < m1 - 1){ pf_r++; if (pf_r == 1152) pf_r = 0; }

        const float xsa[8] = {X0.x, X0.y, X0.z, X0.w, X1.x, X1.y, X1.z, X1.w};
        const float xsb[8] = {X2.x, X2.y, X2.z, X2.w, X3.x, X3.y, X3.z, X3.w};

#pragma unroll
        for (int j = 0; j < 8; j++) u[j] = 0ull;
        const float* wrow = reinterpret_cast<const float*>(Wb + (m - m0)*32) + oh*8;
#pragma unroll
        for (int i = 0; i < I_; i++){
            const ulonglong2* wp = reinterpret_cast<const ulonglong2*>(wrow + i*16);
            ulonglong2 w0 = wp[0];
            u64 w2 = wp[1].x, w3 = wp[1].y;
            u64 xda = pk2(xsa[i], xsa[i]);
            u64 xdb = pk2(xsb[i], xsb[i]);
            u[0] = ffma2(w0.x, xda, u[0]);
            u[1] = ffma2(w0.y, xda, u[1]);
            u[2] = ffma2(w2,   xda, u[2]);
            u[3] = ffma2(w3,   xda, u[3]);
            u[4] = ffma2(w0.x, xdb, u[4]);
            u[5] = ffma2(w0.y, xdb, u[5]);
            u[6] = ffma2(w2,   xdb, u[6]);
            u[7] = ffma2(w3,   xdb, u[7]);
        }

        if (MODE == 0){
#pragma unroll
            for (int j = 0; j < 8; j++) S[j] = fadd2(S[j], u[j]);
        } else {
            float tk[2];
#pragma unroll
            for (int k = 0; k < 2; k++){
                u64 qa = ffma2(u[k*4+0], v[k*4+0], 0ull);
                u64 qb = ffma2(u[k*4+2], v[k*4+2], 0ull);
                qa = ffma2(u[k*4+1], v[k*4+1], qa);
                qb = ffma2(u[k*4+3], v[k*4+3], qb);
                float lo, hi; upk2(fadd2(qa, qb), lo, hi);
                float th = lo + hi;
                tk[k] = th + __shfl_xor_sync(0xffffffffu, th, 1);
            }
            if (MODE == 2){
                tk[0] += bq.x; tk[1] += bq.y;
            } else if (oh == 0){
                reinterpret_cast<float2*>(g_b1)[m*128 + bg] = make_float2(tk[0], tk[1]);
            }
#pragma unroll
            for (int k = 0; k < 2; k++){
                float e = __expf(tk[k]);
                if (oh == 0) E[k] += e;          // E counted ONCE per (b,r,c)
                u64 ed = pk2(e, e);
                S[k*4+0] = ffma2(u[k*4+0], ed, S[k*4+0]);
                S[k*4+1] = ffma2(u[k*4+1], ed, S[k*4+1]);
                S[k*4+2] = ffma2(u[k*4+2], ed, S[k*4+2]);
                S[k*4+3] = ffma2(u[k*4+3], ed, S[k*4+3]);
            }
        }
        if (MODE == 2) bq = bqn;
    }

    // final flush
#pragma unroll
    for (int k = 0; k < 2; k++){
        int b = bg + 128*k;
#pragma unroll
        for (int q = 0; q < 4; q++){
            float lo, hi; upk2(S[k*4+q], lo, hi);
            int o = oh*8 + 2*q;
            atomicAdd(&g_S[(cc*O_ + o    )*B_ + b], lo);
            atomicAdd(&g_S[(cc*O_ + o + 1)*B_ + b], hi);
        }
        if (MODE && oh == 0) atomicAdd(&g_E[cc*B_ + b], E[k]);
    }
}

// ---------------- squash (+ normalization + accumulator re-zero) ----------------
__global__ void __launch_bounds__(128) squash_kernel(float* out, int mode){
    const int c = blockIdx.x;
    const int b = blockIdx.y*128 + threadIdx.x;

    float s[O_];
    float inv;
    if (mode){ inv = 1.0f / g_E[c*B_ + b]; g_E[c*B_ + b] = 0.f; }
    else     { inv = 1.0f / (float)R_; }

    float sq = 0.f;
#pragma unroll
    for (int o = 0; o < O_; o++){
        int sidx = (c*O_ + o)*B_ + b;
        float v = g_S[sidx] * inv;
        g_S[sidx] = 0.f;
        s[o] = v;
        sq += v*v;
    }

    float scale = sq / ((1.0f + sq) * sqrtf(sq + 1e-7f));
    float* dst = (out ? out : g_v) + (b*C_ + c)*O_;
    float4* d4 = reinterpret_cast<float4*>(dst);
#pragma unroll
    for (int q = 0; q < 4; q++)
        d4[q] = make_float4(s[4*q]*scale, s[4*q+1]*scale, s[4*q+2]*scale, s[4*q+3]*scale);
}

// ---------------- launch ----------------
extern "C" void kernel_launch(void* const* d_in, const int* in_sizes, int n_in,
                              void* d_out, int out_size){
    const float* x = (const float*)d_in[0];
    const float* W = (const float*)d_in[1];
    if (n_in >= 2 && in_sizes[0] == R_*C_*O_*I_){ const float* t = x; x = W; W = t; }

    cudaFuncSetAttribute(pass_kernel<0>, cudaFuncAttributeMaxDynamicSharedMemorySize, SMEM0_);
    cudaFuncSetAttribute(pass_kernel<1>, cudaFuncAttributeMaxDynamicSharedMemorySize, SMEM12_);
    cudaFuncSetAttribute(pass_kernel<2>, cudaFuncAttributeMaxDynamicSharedMemorySize, SMEM12_);

    prep_kernel<<<PREP_BLOCKS, 256>>>(x, W);

    dim3 sq_grid(C_, 2);
    pass_kernel<0><<<G0_,  256, SMEM0_>>>();
    squash_kernel<<<sq_grid, 128>>>(nullptr, 0);          // v0
    pass_kernel<1><<<G12_, 256, SMEM12_>>>();
    squash_kernel<<<sq_grid, 128>>>(nullptr, 1);          // v1
    pass_kernel<2><<<G12_, 256, SMEM12_>>>();
    squash_kernel<<<sq_grid, 128>>>((float*)d_out, 1);    // v2 -> output (B,1,C,O,1)
}